// round 2
// baseline (speedup 1.0000x reference)
#include <cuda_runtime.h>
#include <cstdint>
#include <cstdio>

// ---------------- problem constants ----------------
#define BB 64
#define VOC 40
#define EMBD 32
#define L0N 512
#define L1N 1024
#define L2N 2048
#define NSUM (L0N + L1N + L2N)   // 3584
#define LATENT 512
#define STEPS 50
#define START_TOK 39
#define LOGITS_OFF (BB * STEPS)  // 3200

// ---------------- persistent device state (no allocation allowed) ----------------
__device__ float g_h0[BB * L0N];
__device__ float g_h1[BB * L1N];
__device__ float g_h2[BB * L2N];
__device__ float g_n0[BB * L0N];
__device__ float g_n1[BB * L1N];
__device__ float g_n2[BB * L2N];
__device__ float g_v0[BB * 2 * L0N];
__device__ float g_v1[BB * 2 * L1N];
__device__ float g_v2[BB * 2 * L2N];
__device__ float g_x[BB * EMBD];
__device__ int   g_done[BB];

// ---------------- packed f32x2 FMA helpers (Blackwell-only PTX) ----------------
__device__ __forceinline__ void ffma2(uint64_t& d, uint64_t a, uint64_t b) {
    asm("fma.rn.f32x2 %0, %1, %2, %0;" : "+l"(d) : "l"(a), "l"(b));
}
__device__ __forceinline__ uint64_t pack2(float lo, float hi) {
    uint64_t r;
    asm("mov.b64 %0, {%1, %2};" : "=l"(r) : "f"(lo), "f"(hi));
    return r;
}
__device__ __forceinline__ void unpack2(uint64_t v, float& lo, float& hi) {
    asm("mov.b64 {%0, %1}, %2;" : "=f"(lo), "=f"(hi) : "l"(v));
}

__device__ __forceinline__ float sigmoidf_(float x) {
    return 1.0f / (1.0f + expf(-x));
}

// ---------------- init: y = input_vecs @ dense_W + dense_b -> h0|h1|h2 ----------------
// grid (NSUM/256, 8), block 256. Each thread: one output column j, 8 batch rows.
__global__ void __launch_bounds__(256) init_dense_kernel(
    const float* __restrict__ iv,      // [64,512]
    const float* __restrict__ W,       // [512,3584]
    const float* __restrict__ bias)    // [3584]
{
    const int j  = blockIdx.x * 256 + threadIdx.x;
    const int b0 = blockIdx.y * 8;
    __shared__ __align__(16) float s_in[256];
    uint64_t acc[4] = {0ull, 0ull, 0ull, 0ull};

    for (int k0 = 0; k0 < LATENT; k0 += 32) {
        {
            int t = threadIdx.x;
            int kk = t >> 3, row = t & 7;
            s_in[kk * 8 + row] = iv[(b0 + row) * LATENT + (k0 + kk)];
        }
        __syncthreads();
        const uint64_t* s2 = reinterpret_cast<const uint64_t*>(s_in);
#pragma unroll
        for (int kk = 0; kk < 32; kk++) {
            float w = W[(k0 + kk) * NSUM + j];
            uint64_t ww = pack2(w, w);
#pragma unroll
            for (int p = 0; p < 4; p++) ffma2(acc[p], s2[kk * 4 + p], ww);
        }
        __syncthreads();
    }

    const float bj = bias[j];
#pragma unroll
    for (int p = 0; p < 4; p++) {
        float a0, a1;
        unpack2(acc[p], a0, a1);
        float y0 = a0 + bj, y1 = a1 + bj;
        int b_0 = b0 + 2 * p, b_1 = b0 + 2 * p + 1;
        if (j < L0N) {
            g_h0[b_0 * L0N + j] = y0;
            g_h0[b_1 * L0N + j] = y1;
        } else if (j < L0N + L1N) {
            g_h1[b_0 * L1N + (j - L0N)] = y0;
            g_h1[b_1 * L1N + (j - L0N)] = y1;
        } else {
            g_h2[b_0 * L2N + (j - L0N - L1N)] = y0;
            g_h2[b_1 * L2N + (j - L0N - L1N)] = y1;
        }
    }
}

// ---------------- init x = emb[START_TOK], done = false ----------------
__global__ void init_state_kernel(const float* __restrict__ emb) {
    int t = threadIdx.x;
    for (int i = t; i < BB * EMBD; i += 256) {
        g_x[i] = emb[START_TOK * EMBD + (i & (EMBD - 1))];
    }
    if (t < BB) g_done[t] = 0;
}

// ---------------- gates: v = sigmoid([x,h] @ Kg + bg) ----------------
template <int LAYER>
__global__ void __launch_bounds__(256) gates_kernel(
    const float* __restrict__ Kg, const float* __restrict__ bg)
{
    constexpr int IN  = (LAYER == 0) ? EMBD : (LAYER == 1 ? L0N : L1N);
    constexpr int OUT = (LAYER == 0) ? L0N  : (LAYER == 1 ? L1N : L2N);
    constexpr int N   = 2 * OUT;
    constexpr int K   = IN + OUT;

    const float* xin = (LAYER == 0) ? g_x  : (LAYER == 1 ? g_n0 : g_n1);
    const float* hin = (LAYER == 0) ? g_h0 : (LAYER == 1 ? g_h1 : g_h2);
    float* v         = (LAYER == 0) ? g_v0 : (LAYER == 1 ? g_v1 : g_v2);

    const int j  = blockIdx.x * 256 + threadIdx.x;
    const int b0 = blockIdx.y * 8;
    __shared__ __align__(16) float s_in[256];
    uint64_t acc[4] = {0ull, 0ull, 0ull, 0ull};

    for (int k0 = 0; k0 < K; k0 += 32) {
        {
            int t = threadIdx.x;
            int kk = t >> 3, row = t & 7;
            int k = k0 + kk;
            float val;
            if (k < IN) val = xin[(b0 + row) * IN + k];
            else        val = hin[(b0 + row) * OUT + (k - IN)];
            s_in[kk * 8 + row] = val;
        }
        __syncthreads();
        const uint64_t* s2 = reinterpret_cast<const uint64_t*>(s_in);
#pragma unroll
        for (int kk = 0; kk < 32; kk++) {
            float w = Kg[(k0 + kk) * N + j];
            uint64_t ww = pack2(w, w);
#pragma unroll
            for (int p = 0; p < 4; p++) ffma2(acc[p], s2[kk * 4 + p], ww);
        }
        __syncthreads();
    }

    const float bj = bg[j];
#pragma unroll
    for (int p = 0; p < 4; p++) {
        float a0, a1;
        unpack2(acc[p], a0, a1);
        v[(b0 + 2 * p)     * N + j] = sigmoidf_(a0 + bj);
        v[(b0 + 2 * p + 1) * N + j] = sigmoidf_(a1 + bj);
    }
}

// ---------------- candidate + state combine: n = z*h + (1-z)*tanh([x, r*h] @ Kc + bc) ----------------
template <int LAYER>
__global__ void __launch_bounds__(256) cand_kernel(
    const float* __restrict__ Kc, const float* __restrict__ bc)
{
    constexpr int IN  = (LAYER == 0) ? EMBD : (LAYER == 1 ? L0N : L1N);
    constexpr int OUT = (LAYER == 0) ? L0N  : (LAYER == 1 ? L1N : L2N);
    constexpr int N   = OUT;
    constexpr int K   = IN + OUT;

    const float* xin = (LAYER == 0) ? g_x  : (LAYER == 1 ? g_n0 : g_n1);
    const float* hin = (LAYER == 0) ? g_h0 : (LAYER == 1 ? g_h1 : g_h2);
    const float* v   = (LAYER == 0) ? g_v0 : (LAYER == 1 ? g_v1 : g_v2);
    float* n         = (LAYER == 0) ? g_n0 : (LAYER == 1 ? g_n1 : g_n2);

    const int j  = blockIdx.x * 256 + threadIdx.x;
    const int b0 = blockIdx.y * 8;
    __shared__ __align__(16) float s_in[256];
    uint64_t acc[4] = {0ull, 0ull, 0ull, 0ull};

    for (int k0 = 0; k0 < K; k0 += 32) {
        {
            int t = threadIdx.x;
            int kk = t >> 3, row = t & 7;
            int k = k0 + kk;
            int b = b0 + row;
            float val;
            if (k < IN) {
                val = xin[b * IN + k];
            } else {
                int q = k - IN;
                float r = v[b * (2 * OUT) + q];   // r = first half of gates
                val = r * hin[b * OUT + q];
            }
            s_in[kk * 8 + row] = val;
        }
        __syncthreads();
        const uint64_t* s2 = reinterpret_cast<const uint64_t*>(s_in);
#pragma unroll
        for (int kk = 0; kk < 32; kk++) {
            float w = Kc[(k0 + kk) * N + j];
            uint64_t ww = pack2(w, w);
#pragma unroll
            for (int p = 0; p < 4; p++) ffma2(acc[p], s2[kk * 4 + p], ww);
        }
        __syncthreads();
    }

    const float bj = bc[j];
#pragma unroll
    for (int p = 0; p < 4; p++) {
        float a0, a1;
        unpack2(acc[p], a0, a1);
#pragma unroll
        for (int s = 0; s < 2; s++) {
            int b = b0 + 2 * p + s;
            float c  = tanhf(((s == 0) ? a0 : a1) + bj);
            float z  = v[b * (2 * OUT) + OUT + j]; // z = second half of gates
            float hv = hin[b * OUT + j];
            n[b * N + j] = z * hv + (1.0f - z) * c;
        }
    }
}

// ---------------- decode: logits = n2 @ dec_W; argmax; masked writes; state update ----------------
// grid 64 (one block per batch row), block 128 (4 warps x 10 columns each).
__global__ void __launch_bounds__(128) decode_kernel(
    const float* __restrict__ decW,   // [2048, 40]
    const float* __restrict__ emb,    // [40, 32]
    float* __restrict__ out, int step)
{
    const int b    = blockIdx.x;
    const int tid  = threadIdx.x;
    const int w    = tid >> 5;
    const int lane = tid & 31;

    __shared__ float s_logit[VOC];
    __shared__ int s_idx, s_d0;

    float acc[10];
#pragma unroll
    for (int jj = 0; jj < 10; jj++) acc[jj] = 0.0f;

    const float* n2row = g_n2 + b * L2N;
    for (int k = lane; k < L2N; k += 32) {
        float xv = n2row[k];
        const float* wr = decW + k * VOC + w * 10;
#pragma unroll
        for (int jj = 0; jj < 10; jj++) acc[jj] += xv * wr[jj];
    }
#pragma unroll
    for (int jj = 0; jj < 10; jj++) {
        float s = acc[jj];
#pragma unroll
        for (int off = 16; off > 0; off >>= 1)
            s += __shfl_down_sync(0xffffffffu, s, off);
        if (lane == 0) s_logit[w * 10 + jj] = s;
    }
    __syncthreads();

    if (tid == 0) {
        int d0 = g_done[b];
        float best = s_logit[0];
        int bi = 0;
        for (int jj = 1; jj < VOC; jj++) {
            float lv = s_logit[jj];
            if (lv > best) { best = lv; bi = jj; }  // first-max on ties
        }
        s_idx = bi;
        s_d0  = d0;
        int tok = d0 ? 0 : bi;                      // STOP_TOK == 0
        out[b * STEPS + step] = (float)tok;
        g_done[b] = d0 | (bi == 0);
    }
    __syncthreads();

    const int d0  = s_d0;
    const int idx = s_idx;

    float* lo = out + LOGITS_OFF + (b * STEPS + step) * VOC;
    for (int jj = tid; jj < VOC; jj += 128)
        lo[jj] = d0 ? 0.0f : s_logit[jj];

    if (!d0) {
        for (int q = tid; q < L0N; q += 128) g_h0[b * L0N + q] = g_n0[b * L0N + q];
        for (int q = tid; q < L1N; q += 128) g_h1[b * L1N + q] = g_n1[b * L1N + q];
        for (int q = tid; q < L2N; q += 128) g_h2[b * L2N + q] = g_n2[b * L2N + q];
        if (tid < EMBD) g_x[b * EMBD + tid] = emb[idx * EMBD + tid];
    }
}

// ---------------- launch ----------------
extern "C" void kernel_launch(void* const* d_in, const int* in_sizes, int n_in,
                              void* d_out, int out_size)
{
    const float* iv   = (const float*)d_in[0];   // input_vecs [64,512]
    const float* emb  = (const float*)d_in[1];   // emb [40,32]
    const float* dW   = (const float*)d_in[2];   // dense_W [512,3584]
    const float* db   = (const float*)d_in[3];   // dense_b [3584]
    const float* decW = (const float*)d_in[4];   // dec_W [2048,40]
    const float* Kg0  = (const float*)d_in[5];
    const float* bg0  = (const float*)d_in[6];
    const float* Kc0  = (const float*)d_in[7];
    const float* bc0  = (const float*)d_in[8];
    const float* Kg1  = (const float*)d_in[9];
    const float* bg1  = (const float*)d_in[10];
    const float* Kc1  = (const float*)d_in[11];
    const float* bc1  = (const float*)d_in[12];
    const float* Kg2  = (const float*)d_in[13];
    const float* bg2  = (const float*)d_in[14];
    const float* Kc2  = (const float*)d_in[15];
    const float* bc2  = (const float*)d_in[16];
    float* out = (float*)d_out;

    // initial hidden states + start token + done flags
    init_dense_kernel<<<dim3(NSUM / 256, BB / 8), 256>>>(iv, dW, db);
    init_state_kernel<<<1, 256>>>(emb);

    for (int s = 0; s < STEPS; s++) {
        gates_kernel<0><<<dim3((2 * L0N) / 256, BB / 8), 256>>>(Kg0, bg0);
        cand_kernel<0> <<<dim3(L0N / 256,        BB / 8), 256>>>(Kc0, bc0);
        gates_kernel<1><<<dim3((2 * L1N) / 256, BB / 8), 256>>>(Kg1, bg1);
        cand_kernel<1> <<<dim3(L1N / 256,        BB / 8), 256>>>(Kc1, bc1);
        gates_kernel<2><<<dim3((2 * L2N) / 256, BB / 8), 256>>>(Kg2, bg2);
        cand_kernel<2> <<<dim3(L2N / 256,        BB / 8), 256>>>(Kc2, bc2);
        decode_kernel<<<BB, 128>>>(decW, emb, out, s);
    }
}

// round 3
// speedup vs baseline: 3.3198x; 3.3198x over previous
#include <cuda_runtime.h>
#include <cstdint>

// ---------------- problem constants ----------------
#define BB 64
#define VOC 40
#define EMBD 32
#define L0N 512
#define L1N 1024
#define L2N 2048
#define NSUM (L0N + L1N + L2N)   // 3584
#define LATENT 512
#define STEPS 50
#define START_TOK 39
#define LOGITS_OFF (BB * STEPS)  // 3200

#define GRID 128
#define TPB  256

// ---------------- persistent device state (no allocation allowed) ----------------
__device__ float g_h0[BB * L0N];
__device__ float g_h1[BB * L1N];
__device__ float g_h2[BB * L2N];
__device__ float g_n0[BB * L0N];
__device__ float g_n1[BB * L1N];
__device__ float g_n2[BB * L2N];
__device__ float g_v0[BB * 2 * L0N];
__device__ float g_v1[BB * 2 * L1N];
__device__ float g_v2[BB * 2 * L2N];
__device__ float g_x[BB * EMBD];
__device__ int   g_done[BB];
__device__ float g_scr[1 << 20];            // 4MB split-K partial sums

// grid barrier state (monotonic generation; safe across graph replays)
__device__ unsigned          g_barcnt = 0;
__device__ volatile unsigned g_bargen = 0;

// ---------------- helpers ----------------
__device__ __forceinline__ void ffma2(uint64_t& d, uint64_t a, uint64_t b) {
    asm("fma.rn.f32x2 %0, %1, %2, %0;" : "+l"(d) : "l"(a), "l"(b));
}
__device__ __forceinline__ uint64_t pack2(float lo, float hi) {
    uint64_t r;
    asm("mov.b64 %0, {%1, %2};" : "=l"(r) : "f"(lo), "f"(hi));
    return r;
}
__device__ __forceinline__ void unpack2(uint64_t v, float& lo, float& hi) {
    asm("mov.b64 {%0, %1}, %2;" : "=f"(lo), "=f"(hi) : "l"(v));
}
__device__ __forceinline__ float sigmoidf_(float x) {
    return 1.0f / (1.0f + expf(-x));
}

// all 128 blocks are co-resident (GRID < 148 SMs) -> spin barrier is safe
__device__ __forceinline__ void grid_bar() {
    __syncthreads();
    if (threadIdx.x == 0) {
        unsigned gen = g_bargen;
        __threadfence();
        if (atomicAdd(&g_barcnt, 1u) == GRID - 1) {
            g_barcnt = 0;
            __threadfence();
            g_bargen = gen + 1;
        } else {
            while (g_bargen == gen) { }
            __threadfence();
        }
    }
    __syncthreads();
}

// ---------------- split-K GEMM phase ----------------
// out_raw[chunk][b][j] partials into g_scr (as row-pairs over columns).
// Block tile: 128 cols x 64 rows. Thread: 8 cols (4 col-pairs) x 4 rows.
// MODE 0: input = concat[x, h]   (gates / dense with OUT=0)
// MODE 1: input = concat[x, r*h] (candidate; r = first half of v)
template<int IN, int OUT, int NCOL, int TILES, int CHUNKS, int MODE>
__device__ __forceinline__ void gemm_phase(
    const float* __restrict__ W,
    const float* __restrict__ xbuf,
    const float* __restrict__ hbuf,
    const float* __restrict__ vbuf,
    float* __restrict__ s_x)  // smem, 32*66 floats
{
    constexpr int KTOT = IN + OUT;
    constexpr int KC   = (KTOT + CHUNKS - 1) / CHUNKS;

    const int bid = blockIdx.x;
    if (bid < TILES * CHUNKS) {
        const int tile  = bid % TILES;
        const int chunk = bid / TILES;
        const int k0 = chunk * KC;
        const int k1 = (k0 + KC < KTOT) ? (k0 + KC) : KTOT;
        const int jbase = tile * 128;
        const int tid = threadIdx.x;
        const int rg = tid >> 4;   // 0..15 row-group (4 rows each)
        const int c  = tid & 15;   // 0..15 col-thread (8 cols each)

        uint64_t acc[4][4];
#pragma unroll
        for (int cp = 0; cp < 4; cp++)
#pragma unroll
            for (int r = 0; r < 4; r++) acc[cp][r] = 0ull;

        const float* Wc = W + jbase + c * 8;

        for (int kb = k0; kb < k1; kb += 32) {
            const int kt = (k1 - kb < 32) ? (k1 - kb) : 32;
            __syncthreads();
            // stage inputs transposed: s_x[kk*66 + row]
            for (int idx = tid; idx < 64 * 32; idx += TPB) {
                const int kk  = idx & 31;
                const int row = idx >> 5;
                if (kk < kt) {
                    const int kg = kb + kk;
                    float val;
                    if (kg < IN) {
                        val = xbuf[row * IN + kg];
                    } else {
                        const int q = kg - IN;
                        const float hv = hbuf[row * OUT + q];
                        if (MODE == 1)
                            val = vbuf[row * (2 * OUT) + q] * hv;
                        else
                            val = hv;
                    }
                    s_x[kk * 66 + row] = val;
                }
            }
            __syncthreads();

            const float* wrow = Wc + (size_t)kb * NCOL;
            for (int kk = 0; kk < kt; kk++) {
                const ulonglong2* wp = reinterpret_cast<const ulonglong2*>(wrow);
                const ulonglong2 wa = wp[0];
                const ulonglong2 wb2 = wp[1];
                const uint64_t wv0 = wa.x, wv1 = wa.y, wv2 = wb2.x, wv3 = wb2.y;
                const float* xr = s_x + kk * 66 + (rg << 2);
                uint64_t xd[4];
#pragma unroll
                for (int r = 0; r < 4; r++) xd[r] = pack2(xr[r], xr[r]);
#pragma unroll
                for (int r = 0; r < 4; r++) {
                    ffma2(acc[0][r], wv0, xd[r]);
                    ffma2(acc[1][r], wv1, xd[r]);
                    ffma2(acc[2][r], wv2, xd[r]);
                    ffma2(acc[3][r], wv3, xd[r]);
                }
                wrow += NCOL;
            }
        }

        // epilogue: partials to scratch, uint64 = col-pair
        uint64_t* scr = reinterpret_cast<uint64_t*>(g_scr);
#pragma unroll
        for (int r = 0; r < 4; r++) {
            const int row = (rg << 2) + r;
            uint64_t* dst = scr + (size_t)(chunk * 64 + row) * (NCOL / 2)
                                + (jbase >> 1) + (c << 2);
#pragma unroll
            for (int cp = 0; cp < 4; cp++) dst[cp] = acc[cp][r];
        }
    }
    grid_bar();
}

// ---------------- reduce + activation phases ----------------
template<int OUT, int CHUNKS>
__device__ __forceinline__ void reduce_gates(const float* __restrict__ bg,
                                             float* __restrict__ v)
{
    const int NP = 64 * OUT;   // col-pairs total (NCOL/2 = OUT)
    const uint64_t* scr = reinterpret_cast<const uint64_t*>(g_scr);
    for (int p = blockIdx.x * TPB + threadIdx.x; p < NP; p += GRID * TPB) {
        const int row = p / OUT;
        const int jp  = p - row * OUT;
        float s0 = 0.f, s1 = 0.f;
#pragma unroll
        for (int ch = 0; ch < CHUNKS; ch++) {
            float a, b;
            unpack2(scr[(size_t)(ch * 64 + row) * OUT + jp], a, b);
            s0 += a; s1 += b;
        }
        const int j = jp * 2;
        v[row * (2 * OUT) + j]     = sigmoidf_(s0 + bg[j]);
        v[row * (2 * OUT) + j + 1] = sigmoidf_(s1 + bg[j + 1]);
    }
    grid_bar();
}

template<int OUT, int CHUNKS>
__device__ __forceinline__ void reduce_cand(const float* __restrict__ bc,
                                            const float* __restrict__ v,
                                            const float* __restrict__ h,
                                            float* __restrict__ n)
{
    constexpr int HP = OUT / 2;
    const int NP = 64 * HP;
    const uint64_t* scr = reinterpret_cast<const uint64_t*>(g_scr);
    for (int p = blockIdx.x * TPB + threadIdx.x; p < NP; p += GRID * TPB) {
        const int row = p / HP;
        const int jp  = p - row * HP;
        float s0 = 0.f, s1 = 0.f;
#pragma unroll
        for (int ch = 0; ch < CHUNKS; ch++) {
            float a, b;
            unpack2(scr[(size_t)(ch * 64 + row) * HP + jp], a, b);
            s0 += a; s1 += b;
        }
        const int j = jp * 2;
#pragma unroll
        for (int t = 0; t < 2; t++) {
            const float cv = tanhf(((t == 0) ? s0 : s1) + bc[j + t]);
            const float z  = v[row * (2 * OUT) + OUT + j + t];
            const float hv = h[row * OUT + j + t];
            n[row * OUT + j + t] = z * hv + (1.0f - z) * cv;
        }
    }
    grid_bar();
}

__device__ __forceinline__ void reduce_dense(const float* __restrict__ db)
{
    constexpr int HP = NSUM / 2;   // 1792
    const int NP = 64 * HP;
    const uint64_t* scr = reinterpret_cast<const uint64_t*>(g_scr);
    for (int p = blockIdx.x * TPB + threadIdx.x; p < NP; p += GRID * TPB) {
        const int row = p / HP;
        const int jp  = p - row * HP;
        float s0 = 0.f, s1 = 0.f;
#pragma unroll
        for (int ch = 0; ch < 4; ch++) {
            float a, b;
            unpack2(scr[(size_t)(ch * 64 + row) * HP + jp], a, b);
            s0 += a; s1 += b;
        }
        const int j = jp * 2;
        const float y0 = s0 + db[j];
        const float y1 = s1 + db[j + 1];
        if (j < L0N) {
            g_h0[row * L0N + j] = y0; g_h0[row * L0N + j + 1] = y1;
        } else if (j < L0N + L1N) {
            g_h1[row * L1N + (j - L0N)] = y0; g_h1[row * L1N + (j - L0N) + 1] = y1;
        } else {
            g_h2[row * L2N + (j - L0N - L1N)] = y0; g_h2[row * L2N + (j - L0N - L1N) + 1] = y1;
        }
    }
    grid_bar();
}

// ---------------- decode phase ----------------
__device__ __forceinline__ void decode_phase(const float* __restrict__ decW,
                                             const float* __restrict__ emb,
                                             float* __restrict__ out, int step)
{
    if (blockIdx.x < BB) {
        __shared__ float s_logit[VOC];
        __shared__ int s_idx, s_d0;
        const int b    = blockIdx.x;
        const int tid  = threadIdx.x;
        const int w    = tid >> 5;      // 8 warps x 5 cols
        const int lane = tid & 31;

        float acc[5];
#pragma unroll
        for (int jj = 0; jj < 5; jj++) acc[jj] = 0.0f;

        const float* n2row = g_n2 + b * L2N;
        for (int k = lane; k < L2N; k += 32) {
            const float xv = n2row[k];
            const float* wr = decW + k * VOC + w * 5;
#pragma unroll
            for (int jj = 0; jj < 5; jj++) acc[jj] += xv * wr[jj];
        }
#pragma unroll
        for (int jj = 0; jj < 5; jj++) {
            float s = acc[jj];
#pragma unroll
            for (int off = 16; off > 0; off >>= 1)
                s += __shfl_down_sync(0xffffffffu, s, off);
            if (lane == 0) s_logit[w * 5 + jj] = s;
        }
        __syncthreads();

        if (tid == 0) {
            const int d0 = g_done[b];
            float best = s_logit[0];
            int bi = 0;
            for (int jj = 1; jj < VOC; jj++) {
                const float lv = s_logit[jj];
                if (lv > best) { best = lv; bi = jj; }   // first-max on ties
            }
            s_idx = bi;
            s_d0  = d0;
            out[b * STEPS + step] = (float)(d0 ? 0 : bi);   // STOP_TOK == 0
            g_done[b] = d0 | (bi == 0);
        }
        __syncthreads();

        const int d0  = s_d0;
        const int idx = s_idx;

        float* lo = out + LOGITS_OFF + (b * STEPS + step) * VOC;
        for (int jj = tid; jj < VOC; jj += TPB)
            lo[jj] = d0 ? 0.0f : s_logit[jj];

        if (!d0) {
            for (int q = tid; q < L0N; q += TPB) g_h0[b * L0N + q] = g_n0[b * L0N + q];
            for (int q = tid; q < L1N; q += TPB) g_h1[b * L1N + q] = g_n1[b * L1N + q];
            for (int q = tid; q < L2N; q += TPB) g_h2[b * L2N + q] = g_n2[b * L2N + q];
            if (tid < EMBD) g_x[b * EMBD + tid] = emb[idx * EMBD + tid];
        }
    }
    grid_bar();
}

// ---------------- the single persistent kernel ----------------
__global__ void __launch_bounds__(TPB, 1) decoder_kernel(
    const float* __restrict__ iv,   const float* __restrict__ emb,
    const float* __restrict__ dW,   const float* __restrict__ db,
    const float* __restrict__ decW,
    const float* __restrict__ Kg0, const float* __restrict__ bg0,
    const float* __restrict__ Kc0, const float* __restrict__ bc0,
    const float* __restrict__ Kg1, const float* __restrict__ bg1,
    const float* __restrict__ Kc1, const float* __restrict__ bc1,
    const float* __restrict__ Kg2, const float* __restrict__ bg2,
    const float* __restrict__ Kc2, const float* __restrict__ bc2,
    float* __restrict__ out)
{
    __shared__ __align__(16) float s_x[32 * 66];

    // init x / done (block 112 is idle during the 112-block dense gemm)
    if (blockIdx.x == 112) {
        for (int i = threadIdx.x; i < BB * EMBD; i += TPB)
            g_x[i] = emb[START_TOK * EMBD + (i & (EMBD - 1))];
        if (threadIdx.x < BB) g_done[threadIdx.x] = 0;
    }

    // initial hidden states: y = iv @ dense_W + dense_b
    gemm_phase<LATENT, 0, NSUM, 28, 4, 0>(dW, iv, nullptr, nullptr, s_x);
    reduce_dense(db);

    for (int s = 0; s < STEPS; s++) {
        gemm_phase<EMBD, L0N, 2 * L0N,  8, 16, 0>(Kg0, g_x,  g_h0, nullptr, s_x);
        reduce_gates<L0N, 16>(bg0, g_v0);
        gemm_phase<EMBD, L0N, L0N,      4, 32, 1>(Kc0, g_x,  g_h0, g_v0,   s_x);
        reduce_cand<L0N, 32>(bc0, g_v0, g_h0, g_n0);

        gemm_phase<L0N,  L1N, 2 * L1N, 16,  8, 0>(Kg1, g_n0, g_h1, nullptr, s_x);
        reduce_gates<L1N, 8>(bg1, g_v1);
        gemm_phase<L0N,  L1N, L1N,      8, 16, 1>(Kc1, g_n0, g_h1, g_v1,   s_x);
        reduce_cand<L1N, 16>(bc1, g_v1, g_h1, g_n1);

        gemm_phase<L1N,  L2N, 2 * L2N, 32,  4, 0>(Kg2, g_n1, g_h2, nullptr, s_x);
        reduce_gates<L2N, 4>(bg2, g_v2);
        gemm_phase<L1N,  L2N, L2N,     16,  8, 1>(Kc2, g_n1, g_h2, g_v2,   s_x);
        reduce_cand<L2N, 8>(bc2, g_v2, g_h2, g_n2);

        decode_phase(decW, emb, out, s);
    }
}

// ---------------- launch ----------------
extern "C" void kernel_launch(void* const* d_in, const int* in_sizes, int n_in,
                              void* d_out, int out_size)
{
    const float* iv   = (const float*)d_in[0];
    const float* emb  = (const float*)d_in[1];
    const float* dW   = (const float*)d_in[2];
    const float* db   = (const float*)d_in[3];
    const float* decW = (const float*)d_in[4];
    const float* Kg0  = (const float*)d_in[5];
    const float* bg0  = (const float*)d_in[6];
    const float* Kc0  = (const float*)d_in[7];
    const float* bc0  = (const float*)d_in[8];
    const float* Kg1  = (const float*)d_in[9];
    const float* bg1  = (const float*)d_in[10];
    const float* Kc1  = (const float*)d_in[11];
    const float* bc1  = (const float*)d_in[12];
    const float* Kg2  = (const float*)d_in[13];
    const float* bg2  = (const float*)d_in[14];
    const float* Kc2  = (const float*)d_in[15];
    const float* bc2  = (const float*)d_in[16];
    float* out = (float*)d_out;

    decoder_kernel<<<GRID, TPB>>>(iv, emb, dW, db, decW,
                                  Kg0, bg0, Kc0, bc0,
                                  Kg1, bg1, Kc1, bc1,
                                  Kg2, bg2, Kc2, bc2, out);
}

// round 4
// speedup vs baseline: 3.9045x; 1.1761x over previous
#include <cuda_runtime.h>
#include <cstdint>

// ---------------- problem constants ----------------
#define BB 64
#define VOC 40
#define EMBD 32
#define L0N 512
#define L1N 1024
#define L2N 2048
#define NSUM (L0N + L1N + L2N)   // 3584
#define LATENT 512
#define STEPS 50
#define START_TOK 39
#define LOGITS_OFF (BB * STEPS)  // 3200

#define GRID 128
#define TPB  512
#define KBLK 64
#define XPAD 65   // smem row stride (uint64 units) to dodge bank conflicts

// ---------------- persistent device state (no allocation allowed) ----------------
__device__ float g_h0[BB * L0N];
__device__ float g_h1[BB * L1N];
__device__ float g_h2[BB * L2N];
__device__ float g_n0[BB * L0N];
__device__ float g_n1[BB * L1N];
__device__ float g_n2[BB * L2N];
__device__ float g_v0[BB * 2 * L0N];
__device__ float g_v1[BB * 2 * L1N];
__device__ float g_v2[BB * 2 * L2N];
__device__ float g_x[BB * EMBD];
__device__ int   g_done[BB];
__device__ float g_scr[2 << 20];            // 8MB split-K partial sums

// grid barrier state (monotonic generation; safe across graph replays)
__device__ unsigned          g_barcnt = 0;
__device__ volatile unsigned g_bargen = 0;

// ---------------- helpers ----------------
__device__ __forceinline__ void ffma2(uint64_t& d, uint64_t a, uint64_t b) {
    asm("fma.rn.f32x2 %0, %1, %2, %0;" : "+l"(d) : "l"(a), "l"(b));
}
__device__ __forceinline__ uint64_t pack2(float lo, float hi) {
    uint64_t r;
    asm("mov.b64 %0, {%1, %2};" : "=l"(r) : "f"(lo), "f"(hi));
    return r;
}
__device__ __forceinline__ void unpack2(uint64_t v, float& lo, float& hi) {
    asm("mov.b64 {%0, %1}, %2;" : "=f"(lo), "=f"(hi) : "l"(v));
}
__device__ __forceinline__ float sigmoidf_(float x) {
    return 1.0f / (1.0f + expf(-x));
}

// all 128 blocks are co-resident (GRID < 148 SMs) -> spin barrier is safe
__device__ __forceinline__ void grid_bar() {
    __syncthreads();
    if (threadIdx.x == 0) {
        unsigned gen = g_bargen;
        __threadfence();
        if (atomicAdd(&g_barcnt, 1u) == GRID - 1) {
            g_barcnt = 0;
            __threadfence();
            g_bargen = gen + 1;
        } else {
            while (g_bargen == gen) { }
            __threadfence();
        }
    }
    __syncthreads();
}

// ---------------- split-K GEMM phase ----------------
// Block tile: 256 cols x 64 rows, K-chunked. Thread: 8 cols (4 pairs) x 4 rows.
// Partials -> g_scr[chunk][row][colpair].
// MODE 0: input = concat[x, h];  MODE 1: input = concat[x, r*h] (r = 1st half of v)
template<int IN, int OUT, int NCOL, int TILES, int CHUNKS, int MODE>
__device__ __forceinline__ void gemm_phase(
    const float* __restrict__ W,
    const float* __restrict__ xbuf,
    const float* __restrict__ hbuf,
    const float* __restrict__ vbuf,
    uint64_t* __restrict__ s_x2)   // smem: KBLK * XPAD uint64
{
    constexpr int KTOT = IN + OUT;
    constexpr int KC   = (KTOT + CHUNKS - 1) / CHUNKS;

    const int bid = blockIdx.x;
    if (bid < TILES * CHUNKS) {
        const int tile  = bid % TILES;
        const int chunk = bid / TILES;
        const int k0 = chunk * KC;
        const int k1 = (k0 + KC < KTOT) ? (k0 + KC) : KTOT;
        const int jbase = tile * 256;
        const int tid = threadIdx.x;
        const int c  = tid & 31;   // col-thread: 8 cols
        const int rg = tid >> 5;   // row-group: 4 rows

        uint64_t acc[4][4];
#pragma unroll
        for (int cp = 0; cp < 4; cp++)
#pragma unroll
            for (int r = 0; r < 4; r++) acc[cp][r] = 0ull;

        const float* Wc = W + jbase + c * 8;

        for (int kb = k0; kb < k1; kb += KBLK) {
            const int kt = (k1 - kb < KBLK) ? (k1 - kb) : KBLK;
            __syncthreads();
            // stage inputs: lanes stride over k (coalesced gmem), duplicated pair in smem
            for (int idx = tid; idx < 64 * KBLK; idx += TPB) {
                const int kk  = idx & (KBLK - 1);
                const int row = idx >> 6;
                if (kk < kt) {
                    const int kg = kb + kk;
                    float val;
                    if (kg < IN) {
                        val = xbuf[row * IN + kg];
                    } else {
                        const int q = kg - IN;
                        const float hv = hbuf[row * OUT + q];
                        if (MODE == 1)
                            val = vbuf[row * (2 * OUT) + q] * hv;
                        else
                            val = hv;
                    }
                    s_x2[kk * XPAD + row] = pack2(val, val);
                }
            }
            __syncthreads();

            const float* wrow = Wc + (size_t)kb * NCOL;
#pragma unroll 4
            for (int kk = 0; kk < kt; kk++) {
                const ulonglong2 wa  = *reinterpret_cast<const ulonglong2*>(wrow);
                const ulonglong2 wb2 = *reinterpret_cast<const ulonglong2*>(wrow + 4);
                const uint64_t* xr = s_x2 + kk * XPAD + (rg << 2);
#pragma unroll
                for (int r = 0; r < 4; r++) {
                    const uint64_t xd = xr[r];
                    ffma2(acc[0][r], wa.x,  xd);
                    ffma2(acc[1][r], wa.y,  xd);
                    ffma2(acc[2][r], wb2.x, xd);
                    ffma2(acc[3][r], wb2.y, xd);
                }
                wrow += NCOL;
            }
        }

        // epilogue: partials to scratch (uint64 = col-pair), coalesced
        uint64_t* scr = reinterpret_cast<uint64_t*>(g_scr);
#pragma unroll
        for (int r = 0; r < 4; r++) {
            const int row = (rg << 2) + r;
            uint64_t* dst = scr + (size_t)(chunk * 64 + row) * (NCOL / 2)
                                + (jbase >> 1) + (c << 2);
#pragma unroll
            for (int cp = 0; cp < 4; cp++) dst[cp] = acc[cp][r];
        }
    }
    grid_bar();
}

// ---------------- reduce + activation phases ----------------
template<int OUT, int CHUNKS>
__device__ __forceinline__ void reduce_gates(const float* __restrict__ bg,
                                             float* __restrict__ v)
{
    const int NP = 64 * OUT;   // col-pairs (NCOL/2 = OUT)
    const uint64_t* scr = reinterpret_cast<const uint64_t*>(g_scr);
    for (int p = blockIdx.x * TPB + threadIdx.x; p < NP; p += GRID * TPB) {
        const int row = p / OUT;
        const int jp  = p - row * OUT;
        float s0 = 0.f, s1 = 0.f;
#pragma unroll 8
        for (int ch = 0; ch < CHUNKS; ch++) {
            float a, b;
            unpack2(scr[(size_t)(ch * 64 + row) * OUT + jp], a, b);
            s0 += a; s1 += b;
        }
        const int j = jp * 2;
        v[row * (2 * OUT) + j]     = sigmoidf_(s0 + bg[j]);
        v[row * (2 * OUT) + j + 1] = sigmoidf_(s1 + bg[j + 1]);
    }
    grid_bar();
}

template<int OUT, int CHUNKS>
__device__ __forceinline__ void reduce_cand(const float* __restrict__ bc,
                                            const float* __restrict__ v,
                                            const float* __restrict__ h,
                                            float* __restrict__ n)
{
    constexpr int HP = OUT / 2;
    const int NP = 64 * HP;
    const uint64_t* scr = reinterpret_cast<const uint64_t*>(g_scr);
    for (int p = blockIdx.x * TPB + threadIdx.x; p < NP; p += GRID * TPB) {
        const int row = p / HP;
        const int jp  = p - row * HP;
        float s0 = 0.f, s1 = 0.f;
#pragma unroll 8
        for (int ch = 0; ch < CHUNKS; ch++) {
            float a, b;
            unpack2(scr[(size_t)(ch * 64 + row) * HP + jp], a, b);
            s0 += a; s1 += b;
        }
        const int j = jp * 2;
#pragma unroll
        for (int t = 0; t < 2; t++) {
            const float cv = tanhf(((t == 0) ? s0 : s1) + bc[j + t]);
            const float z  = v[row * (2 * OUT) + OUT + j + t];
            const float hv = h[row * OUT + j + t];
            n[row * OUT + j + t] = z * hv + (1.0f - z) * cv;
        }
    }
    grid_bar();
}

__device__ __forceinline__ void reduce_dense(const float* __restrict__ db)
{
    constexpr int HP = NSUM / 2;   // 1792
    const int NP = 64 * HP;
    const uint64_t* scr = reinterpret_cast<const uint64_t*>(g_scr);
    for (int p = blockIdx.x * TPB + threadIdx.x; p < NP; p += GRID * TPB) {
        const int row = p / HP;
        const int jp  = p - row * HP;
        float s0 = 0.f, s1 = 0.f;
#pragma unroll
        for (int ch = 0; ch < 8; ch++) {
            float a, b;
            unpack2(scr[(size_t)(ch * 64 + row) * HP + jp], a, b);
            s0 += a; s1 += b;
        }
        const int j = jp * 2;
        const float y0 = s0 + db[j];
        const float y1 = s1 + db[j + 1];
        if (j < L0N) {
            g_h0[row * L0N + j] = y0; g_h0[row * L0N + j + 1] = y1;
        } else if (j < L0N + L1N) {
            g_h1[row * L1N + (j - L0N)] = y0; g_h1[row * L1N + (j - L0N) + 1] = y1;
        } else {
            g_h2[row * L2N + (j - L0N - L1N)] = y0; g_h2[row * L2N + (j - L0N - L1N) + 1] = y1;
        }
    }
    grid_bar();
}

// ---------------- decode phase ----------------
__device__ __forceinline__ void decode_phase(const float* __restrict__ decW,
                                             const float* __restrict__ emb,
                                             float* __restrict__ out, int step)
{
    if (blockIdx.x < BB) {
        __shared__ float s_logit[VOC];
        __shared__ int s_idx, s_d0;
        const int b    = blockIdx.x;
        const int tid  = threadIdx.x;
        const int w    = tid >> 5;      // 16 warps
        const int lane = tid & 31;

        if (w < 8) {   // 8 warps x 5 logit cols
            float acc[5];
#pragma unroll
            for (int jj = 0; jj < 5; jj++) acc[jj] = 0.0f;

            const float* n2row = g_n2 + b * L2N;
            for (int k = lane; k < L2N; k += 32) {
                const float xv = n2row[k];
                const float* wr = decW + k * VOC + w * 5;
#pragma unroll
                for (int jj = 0; jj < 5; jj++) acc[jj] += xv * wr[jj];
            }
#pragma unroll
            for (int jj = 0; jj < 5; jj++) {
                float s = acc[jj];
#pragma unroll
                for (int off = 16; off > 0; off >>= 1)
                    s += __shfl_down_sync(0xffffffffu, s, off);
                if (lane == 0) s_logit[w * 5 + jj] = s;
            }
        }
        __syncthreads();

        if (tid == 0) {
            const int d0 = g_done[b];
            float best = s_logit[0];
            int bi = 0;
            for (int jj = 1; jj < VOC; jj++) {
                const float lv = s_logit[jj];
                if (lv > best) { best = lv; bi = jj; }   // first-max on ties
            }
            s_idx = bi;
            s_d0  = d0;
            out[b * STEPS + step] = (float)(d0 ? 0 : bi);   // STOP_TOK == 0
            g_done[b] = d0 | (bi == 0);
        }
        __syncthreads();

        const int d0  = s_d0;
        const int idx = s_idx;

        float* lo = out + LOGITS_OFF + (b * STEPS + step) * VOC;
        for (int jj = tid; jj < VOC; jj += TPB)
            lo[jj] = d0 ? 0.0f : s_logit[jj];

        if (!d0) {
            for (int q = tid; q < L0N; q += TPB) g_h0[b * L0N + q] = g_n0[b * L0N + q];
            for (int q = tid; q < L1N; q += TPB) g_h1[b * L1N + q] = g_n1[b * L1N + q];
            for (int q = tid; q < L2N; q += TPB) g_h2[b * L2N + q] = g_n2[b * L2N + q];
            if (tid < EMBD) g_x[b * EMBD + tid] = emb[idx * EMBD + tid];
        }
    }
    grid_bar();
}

// ---------------- the single persistent kernel ----------------
__global__ void __launch_bounds__(TPB, 1) decoder_kernel(
    const float* __restrict__ iv,   const float* __restrict__ emb,
    const float* __restrict__ dW,   const float* __restrict__ db,
    const float* __restrict__ decW,
    const float* __restrict__ Kg0, const float* __restrict__ bg0,
    const float* __restrict__ Kc0, const float* __restrict__ bc0,
    const float* __restrict__ Kg1, const float* __restrict__ bg1,
    const float* __restrict__ Kc1, const float* __restrict__ bc1,
    const float* __restrict__ Kg2, const float* __restrict__ bg2,
    const float* __restrict__ Kc2, const float* __restrict__ bc2,
    float* __restrict__ out)
{
    __shared__ __align__(16) uint64_t s_x2[KBLK * XPAD];

    // init x / done (blocks 112..127 idle during the 112-block dense gemm)
    if (blockIdx.x == 112) {
        for (int i = threadIdx.x; i < BB * EMBD; i += TPB)
            g_x[i] = emb[START_TOK * EMBD + (i & (EMBD - 1))];
        if (threadIdx.x < BB) g_done[threadIdx.x] = 0;
    }

    // initial hidden states: y = iv @ dense_W + dense_b
    gemm_phase<LATENT, 0, NSUM, 14, 8, 0>(dW, iv, nullptr, nullptr, s_x2);
    reduce_dense(db);

    for (int s = 0; s < STEPS; s++) {
        gemm_phase<EMBD, L0N, 2 * L0N,  4, 32, 0>(Kg0, g_x,  g_h0, nullptr, s_x2);
        reduce_gates<L0N, 32>(bg0, g_v0);
        gemm_phase<EMBD, L0N, L0N,      2, 64, 1>(Kc0, g_x,  g_h0, g_v0,   s_x2);
        reduce_cand<L0N, 64>(bc0, g_v0, g_h0, g_n0);

        gemm_phase<L0N,  L1N, 2 * L1N,  8, 16, 0>(Kg1, g_n0, g_h1, nullptr, s_x2);
        reduce_gates<L1N, 16>(bg1, g_v1);
        gemm_phase<L0N,  L1N, L1N,      4, 32, 1>(Kc1, g_n0, g_h1, g_v1,   s_x2);
        reduce_cand<L1N, 32>(bc1, g_v1, g_h1, g_n1);

        gemm_phase<L1N,  L2N, 2 * L2N, 16,  8, 0>(Kg2, g_n1, g_h2, nullptr, s_x2);
        reduce_gates<L2N, 8>(bg2, g_v2);
        gemm_phase<L1N,  L2N, L2N,      8, 16, 1>(Kc2, g_n1, g_h2, g_v2,   s_x2);
        reduce_cand<L2N, 16>(bc2, g_v2, g_h2, g_n2);

        decode_phase(decW, emb, out, s);
    }
}

// ---------------- launch ----------------
extern "C" void kernel_launch(void* const* d_in, const int* in_sizes, int n_in,
                              void* d_out, int out_size)
{
    const float* iv   = (const float*)d_in[0];
    const float* emb  = (const float*)d_in[1];
    const float* dW   = (const float*)d_in[2];
    const float* db   = (const float*)d_in[3];
    const float* decW = (const float*)d_in[4];
    const float* Kg0  = (const float*)d_in[5];
    const float* bg0  = (const float*)d_in[6];
    const float* Kc0  = (const float*)d_in[7];
    const float* bc0  = (const float*)d_in[8];
    const float* Kg1  = (const float*)d_in[9];
    const float* bg1  = (const float*)d_in[10];
    const float* Kc1  = (const float*)d_in[11];
    const float* bc1  = (const float*)d_in[12];
    const float* Kg2  = (const float*)d_in[13];
    const float* bg2  = (const float*)d_in[14];
    const float* Kc2  = (const float*)d_in[15];
    const float* bc2  = (const float*)d_in[16];
    float* out = (float*)d_out;

    decoder_kernel<<<GRID, TPB>>>(iv, emb, dW, db, decW,
                                  Kg0, bg0, Kc0, bc0,
                                  Kg1, bg1, Kc1, bc1,
                                  Kg2, bg2, Kc2, bc2, out);
}